// round 1
// baseline (speedup 1.0000x reference)
#include <cuda_runtime.h>
#include <math.h>

// Problem constants (fixed by the reference)
#define BATCH_SAMPLES 320000
#define NFRAMES 1000
#define HOP 320
#define NFFT 1024
#define N2 512          // complex FFT size (packed real)
#define NBINS 513
#define NMELS 128
#define WINLEN 800
#define WOFF 112        // (1024-800)/2
#define PREEMPH 0.97f

// Scratch: per-mel nonzero bin range (built each launch by a tiny setup kernel).
__device__ int g_mel_start[NMELS];
__device__ int g_mel_end[NMELS];

__global__ void build_mel_ranges_kernel(const float* __restrict__ mel) {
    int m = threadIdx.x;
    if (m >= NMELS) return;
    const float* row = mel + (size_t)m * NBINS;
    int s = NBINS, e = -1;
    for (int f = 0; f < NBINS; ++f) {
        float w = row[f];
        if (w != 0.0f) { if (f < s) s = f; e = f; }
    }
    if (e < 0) { s = 1; e = 0; }   // empty filter -> empty loop
    g_mel_start[m] = s;
    g_mel_end[m]   = e;
}

// One block per (frame t, batch b). 256 threads.
// Pipeline: preemph+window -> bitrev pack -> 9-stage radix-2 DIT FFT (512 cplx)
// -> real-FFT split -> power -> sparse mel -> log -> store.
__global__ __launch_bounds__(256) void logmel_kernel(
    const float* __restrict__ x,
    const float* __restrict__ mel,
    float* __restrict__ out)
{
    __shared__ float buf[NFFT];     // windowed frame
    __shared__ float re[N2];
    __shared__ float im[N2];
    __shared__ float twc[256];      // tw[j] = exp(-2*pi*i*j/512)
    __shared__ float tws[256];
    __shared__ float powbuf[NBINS];

    const int tid = threadIdx.x;
    const int t = blockIdx.x;
    const int b = blockIdx.y;
    const float* __restrict__ xb = x + (size_t)b * BATCH_SAMPLES;

    // Twiddle table (one per thread)
    {
        float ang = -(float)M_PI * (float)tid * (1.0f / 256.0f);
        float s, c;
        sincosf(ang, &s, &c);
        tws[tid] = s; twc[tid] = c;
    }

    // Windowed, pre-emphasized, zero-padded frame.
    // frame sample n maps to y index i = t*HOP + n - 512,
    // y[i] = x[i+1] - 0.97*x[i] for i in [0, 319998], else 0.
    for (int n = tid; n < NFFT; n += 256) {
        float v = 0.0f;
        if (n >= WOFF && n < WOFF + WINLEN) {
            int i = t * HOP + n - 512;
            float y = 0.0f;
            if (i >= 0 && i <= BATCH_SAMPLES - 2) {
                y = xb[i + 1] - PREEMPH * xb[i];
            }
            float w = 0.5f - 0.5f * cosf((2.0f * (float)M_PI / 799.0f) * (float)(n - WOFF));
            v = w * y;
        }
        buf[n] = v;
    }
    __syncthreads();

    // Pack even/odd into complex and bit-reverse (9 bits) for DIT.
    for (int j = tid; j < N2; j += 256) {
        int p = (int)(__brev((unsigned)j) >> 23);
        re[j] = buf[2 * p];
        im[j] = buf[2 * p + 1];
    }
    __syncthreads();

    // 9 radix-2 DIT stages; 256 butterflies per stage = 1 per thread.
    #pragma unroll
    for (int s = 1; s <= 9; ++s) {
        const int half = 1 << (s - 1);
        const int pos  = tid & (half - 1);
        const int grp  = tid >> (s - 1);
        const int base = (grp << s) + pos;
        const int twi  = pos << (9 - s);   // pos * (256/half)
        float c  = twc[twi], sn = tws[twi];
        float br = re[base + half], bi = im[base + half];
        float tr = fmaf(br, c, -bi * sn);
        float ti = fmaf(br, sn,  bi * c);
        float ar = re[base], ai = im[base];
        re[base]        = ar + tr;
        im[base]        = ai + ti;
        re[base + half] = ar - tr;
        im[base + half] = ai - ti;
        __syncthreads();
    }

    // Real-FFT split + power: X[k] = Xe[k] + W_N^k * Xo[k], k = 0..512
    for (int k = tid; k <= N2; k += 256) {
        int kk = k & (N2 - 1);
        int k2 = (N2 - k) & (N2 - 1);
        float zr = re[kk], zi = im[kk];
        float ur = re[k2], ui = im[k2];
        float xer  = 0.5f * (zr + ur);
        float xei  = 0.5f * (zi - ui);
        float xodr = 0.5f * (zi + ui);
        float xodi = -0.5f * (zr - ur);
        float ang = -(float)M_PI * (float)k * (1.0f / 512.0f);
        float ws, wc;
        sincosf(ang, &ws, &wc);
        float xr = xer + wc * xodr - ws * xodi;
        float xi = xei + wc * xodi + ws * xodr;
        powbuf[k] = xr * xr + xi * xi;
    }
    __syncthreads();

    // Sparse mel: each mel filter only touches a contiguous bin range.
    if (tid < NMELS) {
        const int m = tid;
        const int s0 = g_mel_start[m];
        const int e0 = g_mel_end[m];
        const float* __restrict__ row = mel + (size_t)m * NBINS;
        float acc = 0.0f;
        for (int f = s0; f <= e0; ++f) {
            acc = fmaf(row[f], powbuf[f], acc);
        }
        out[((size_t)(b * NMELS + m)) * NFRAMES + t] =
            (logf(acc + 1e-5f) + 4.5f) * 0.2f;
    }
}

extern "C" void kernel_launch(void* const* d_in, const int* in_sizes, int n_in,
                              void* d_out, int out_size) {
    const float* x   = (const float*)d_in[0];
    // d_in[1] = fourier_basis (unused: FFT computes it exactly)
    const float* mel = (const float*)d_in[2];
    float* out = (float*)d_out;

    int batch = in_sizes[0] / BATCH_SAMPLES;   // 32

    build_mel_ranges_kernel<<<1, NMELS>>>(mel);

    dim3 grid(NFRAMES, batch);
    logmel_kernel<<<grid, 256>>>(x, mel, out);
}

// round 2
// speedup vs baseline: 3.9865x; 3.9865x over previous
#include <cuda_runtime.h>
#include <math.h>

#define BATCH_SAMPLES 320000
#define NFRAMES 1000
#define HOP 320
#define N2 512          // complex FFT size (packed real FFT of 1024)
#define NBINS 513
#define NMELS 128
#define PREEMPH 0.97f

// per-mel nonzero bin range (rebuilt every launch; deterministic)
__device__ int g_mel_start[NMELS];
__device__ int g_mel_end[NMELS];

__global__ void build_mel_ranges_kernel(const float* __restrict__ mel) {
    int m = threadIdx.x;
    if (m >= NMELS) return;
    const float* row = mel + (size_t)m * NBINS;
    int s = NBINS, e = -1;
    for (int f = 0; f < NBINS; ++f) {
        if (row[f] != 0.0f) { if (f < s) s = f; e = f; }
    }
    if (e < 0) { s = 1; e = 0; }
    g_mel_start[m] = s;
    g_mel_end[m]   = e;
}

// bank-skewed shared addressing: strides 1, 8, 64 all ~conflict-free
__device__ __forceinline__ int phys(int i) { return i + (i >> 3); }
// octal digit reversal of a 9-bit index (3 octal digits)
__device__ __forceinline__ int dr_oct(int k) {
    return ((k & 7) << 6) | (k & 56) | ((k >> 6) & 7);
}

// natural-order 8-point DFT (forward, W8 = e^{-i pi/4}), in registers
__device__ __forceinline__ void dft8(float* r, float* i) {
    const float s22 = 0.70710678118654752f;
    float br[8], bi[8];
    br[0] = r[0] + r[4];  bi[0] = i[0] + i[4];
    br[4] = r[0] - r[4];  bi[4] = i[0] - i[4];
    float t1r = r[1] - r[5], t1i = i[1] - i[5];
    br[1] = r[1] + r[5];  bi[1] = i[1] + i[5];
    float t2r = r[2] - r[6], t2i = i[2] - i[6];
    br[2] = r[2] + r[6];  bi[2] = i[2] + i[6];
    float t3r = r[3] - r[7], t3i = i[3] - i[7];
    br[3] = r[3] + r[7];  bi[3] = i[3] + i[7];
    br[5] = s22 * (t1r + t1i);  bi[5] = s22 * (t1i - t1r);   // * W8^1
    br[6] = t2i;                bi[6] = -t2r;                // * W8^2 = -i
    br[7] = s22 * (t3i - t3r);  bi[7] = -s22 * (t3r + t3i);  // * W8^3
    float c0r = br[0] + br[2], c0i = bi[0] + bi[2];
    float c2r = br[0] - br[2], c2i = bi[0] - bi[2];
    float c1r = br[1] + br[3], c1i = bi[1] + bi[3];
    float d1r = br[1] - br[3], d1i = bi[1] - bi[3];
    float c3r = d1i, c3i = -d1r;
    float c4r = br[4] + br[6], c4i = bi[4] + bi[6];
    float c6r = br[4] - br[6], c6i = bi[4] - bi[6];
    float c5r = br[5] + br[7], c5i = bi[5] + bi[7];
    float d3r = br[5] - br[7], d3i = bi[5] - bi[7];
    float c7r = d3i, c7i = -d3r;
    r[0] = c0r + c1r;  i[0] = c0i + c1i;
    r[4] = c0r - c1r;  i[4] = c0i - c1i;
    r[2] = c2r + c3r;  i[2] = c2i + c3i;
    r[6] = c2r - c3r;  i[6] = c2i - c3i;
    r[1] = c4r + c5r;  i[1] = c4i + c5i;
    r[5] = c4r - c5r;  i[5] = c4i - c5i;
    r[3] = c6r + c7r;  i[3] = c6i + c7i;
    r[7] = c6r - c7r;  i[7] = c6i - c7i;
}

// apply out[k] *= w^k for k=1..7, w = (wr, wi)
__device__ __forceinline__ void twiddle8(float* ar, float* ai, float wr, float wi) {
    float cwr = wr, cwi = wi;
    #pragma unroll
    for (int k = 1; k < 8; ++k) {
        float tr = ar[k] * cwr - ai[k] * cwi;
        ai[k]    = ar[k] * cwi + ai[k] * cwr;
        ar[k]    = tr;
        float nr = cwr * wr - cwi * wi;
        cwi      = cwr * wi + cwi * wr;
        cwr      = nr;
    }
}

__device__ __forceinline__ float yval(const float* __restrict__ xb, int i) {
    return (i >= 0 && i <= BATCH_SAMPLES - 2) ? (xb[i + 1] - PREEMPH * xb[i]) : 0.0f;
}

// one frame per 64-thread block
__global__ __launch_bounds__(64) void logmel_kernel(
    const float* __restrict__ x,
    const float* __restrict__ mel,
    float* __restrict__ out)
{
    __shared__ float sre[576];
    __shared__ float sim[576];
    __shared__ float powbuf[NBINS];

    const int tid = threadIdx.x;
    const int t   = blockIdx.x;
    const int b   = blockIdx.y;
    const float* __restrict__ xb = x + (size_t)b * BATCH_SAMPLES;
    const int base = t * HOP - 512;

    // ---- windowed, pre-emphasized, zero-padded frame -> shared (skewed) ----
    // frame sample n: y index i = base + n; hann on n in [112, 912)
    const float wk = 2.0f * (float)M_PI / 799.0f;
    #pragma unroll
    for (int p = tid; p < N2; p += 64) {
        int n0 = 2 * p, n1 = 2 * p + 1;
        float v0 = 0.0f, v1 = 0.0f;
        if (n0 >= 112 && n0 < 912) {
            float w = 0.5f - 0.5f * __cosf(wk * (float)(n0 - 112));
            v0 = w * yval(xb, base + n0);
        }
        if (n1 >= 112 && n1 < 912) {
            float w = 0.5f - 0.5f * __cosf(wk * (float)(n1 - 112));
            v1 = w * yval(xb, base + n1);
        }
        int j = phys(p);
        sre[j] = v0;
        sim[j] = v1;
    }
    __syncthreads();

    float ar[8], ai[8];

    // ---- stage 1: span 64, twiddle W_512^{t*k} ----
    #pragma unroll
    for (int m = 0; m < 8; ++m) {
        int j = phys(tid + (m << 6));
        ar[m] = sre[j]; ai[m] = sim[j];
    }
    dft8(ar, ai);
    {
        float s1, c1;
        __sincosf(-((float)M_PI / 256.0f) * (float)tid, &s1, &c1);
        twiddle8(ar, ai, c1, s1);
    }
    #pragma unroll
    for (int k = 0; k < 8; ++k) {
        int j = phys(tid + (k << 6));
        sre[j] = ar[k]; sim[j] = ai[k];
    }
    __syncthreads();

    // ---- stage 2: span 8, twiddle W_64^{p*k} ----
    {
        const int G = tid >> 3, p = tid & 7;
        const int b0 = (G << 6) + p;
        #pragma unroll
        for (int m = 0; m < 8; ++m) {
            int j = phys(b0 + (m << 3));
            ar[m] = sre[j]; ai[m] = sim[j];
        }
        dft8(ar, ai);
        float s1, c1;
        __sincosf(-((float)M_PI / 32.0f) * (float)p, &s1, &c1);
        twiddle8(ar, ai, c1, s1);
        #pragma unroll
        for (int k = 0; k < 8; ++k) {
            int j = phys(b0 + (k << 3));
            sre[j] = ar[k]; sim[j] = ai[k];
        }
    }
    __syncthreads();

    // ---- stage 3: span 1, no twiddle ----
    {
        const int b0 = tid << 3;
        #pragma unroll
        for (int m = 0; m < 8; ++m) {
            int j = phys(b0 + m);
            ar[m] = sre[j]; ai[m] = sim[j];
        }
        dft8(ar, ai);
        #pragma unroll
        for (int k = 0; k < 8; ++k) {
            int j = phys(b0 + k);
            sre[j] = ar[k]; sim[j] = ai[k];
        }
    }
    __syncthreads();

    // ---- real-FFT split + power; Z[k] lives at dr_oct(k) ----
    for (int k = tid; k <= N2; k += 64) {
        int kk = k & (N2 - 1);
        int k2 = (N2 - k) & (N2 - 1);
        int j1 = phys(dr_oct(kk));
        int j2 = phys(dr_oct(k2));
        float zr = sre[j1], zi = sim[j1];
        float ur = sre[j2], ui = sim[j2];
        float xer  = 0.5f * (zr + ur);
        float xei  = 0.5f * (zi - ui);
        float xodr = 0.5f * (zi + ui);
        float xodi = -0.5f * (zr - ur);
        float ws, wc;
        __sincosf(-((float)M_PI / 512.0f) * (float)k, &ws, &wc);
        float xr = xer + wc * xodr - ws * xodi;
        float xi = xei + wc * xodi + ws * xodr;
        powbuf[k] = xr * xr + xi * xi;
    }
    __syncthreads();

    // ---- sparse mel + log; 2 mels per thread ----
    #pragma unroll
    for (int mm = 0; mm < 2; ++mm) {
        const int m = tid + (mm << 6);
        const int s0 = g_mel_start[m];
        const int e0 = g_mel_end[m];
        const float* __restrict__ row = mel + (size_t)m * NBINS;
        float acc = 0.0f;
        for (int f = s0; f <= e0; ++f) {
            acc = fmaf(__ldg(row + f), powbuf[f], acc);
        }
        out[((size_t)(b * NMELS + m)) * NFRAMES + t] =
            (logf(acc + 1e-5f) + 4.5f) * 0.2f;
    }
}

extern "C" void kernel_launch(void* const* d_in, const int* in_sizes, int n_in,
                              void* d_out, int out_size) {
    const float* x   = (const float*)d_in[0];
    // d_in[1] = fourier_basis (unused — FFT computes the same transform)
    const float* mel = (const float*)d_in[2];
    float* out = (float*)d_out;

    int batch = in_sizes[0] / BATCH_SAMPLES;   // 32

    build_mel_ranges_kernel<<<1, NMELS>>>(mel);

    dim3 grid(NFRAMES, batch);
    logmel_kernel<<<grid, 64>>>(x, mel, out);
}